// round 14
// baseline (speedup 1.0000x reference)
#include <cuda_runtime.h>
#include <cstdint>
#include <math.h>

// ---------------- problem constants ----------------
#define NB   8
#define NC   80
#define NH   200
#define NW   304
#define HW   (NH*NW)            // 60800
#define CHW  (NC*HW)            // 4,864,000
#define KTOP 10000
#define PAD  512

// Histogram rebased at the keep-cut: kept scores have sb >= 0x3F4CCCCE.
#define BIN_BASE 0x3F4CCCCEu
#define NBINS 7168              // 7 * 1024

// Hot/cold key split at fine-bin 1966 boundary (score ~0.85996).
#define HOT_BITS 0x3F5C28CEu
#define HOT_FBIN 1966
#define HOTCAP  65536
#define COLDCAP 131072

#define ELEM_PER_BLK 2048
#define BLKS_PER_IMG (CHW/ELEM_PER_BLK)   // 2375 exact
#define SLICE_CAP 256

#define IMG_W_M1 2431.0f
#define IMG_H_M1 1599.0f
#define BBOX_CLIP 4.135166556742356f   // log(1000/16)

// Exact keep-cut (verified rounds 5-13): score > 0.80.
#define KEEP_CUT 0.80f
// Pass-1 loose cut T=0.79: x > xthr(si) = -log(si/T^2 - 1); logit margin
// to the exact cut >= 0.026 -> pass-1 can only over-keep.
#define INV_T2 1.602307322f        // 1/0.6241
#define SI_MIN 0.6242f

// ---------------- device scratch ----------------
__device__ float               g_siou[NB*HW];
__device__ float               g_xthr[NB*HW];
__device__ int                 g_fhist[NB][NBINS];
__device__ int                 g_cabove[NB][NBINS];
__device__ int                 g_cursor[NB][NBINS];
__device__ int                 g_FB[NB];
__device__ int                 g_hotcnt[NB];
__device__ int                 g_coldcnt[NB];
__device__ int                 g_hotovf[NB];
__device__ unsigned long long  g_hot[NB][HOTCAP];
__device__ unsigned long long  g_cold[NB][COLDCAP];
__device__ unsigned long long  g_sorted[NB][KTOP+PAD];

// ---------------- reference-exact sigmoid: FUSED Cephes exp ----------------
// (verified bit-exact vs reference in rounds 5-13: rel_err 7.2e-9)
__device__ __forceinline__ float ref_expf(float a) {
    float x = fminf(a, 88.3762626647950f);
    x = fmaxf(x, -88.3762626647949f);
    float fx = floorf(fmaf(x, 1.44269504088896341f, 0.5f));
    float r = fmaf(-0.693359375f, fx, x);
    r = fmaf(2.12194440e-4f, fx, r);
    float z = __fmul_rn(r, r);
    float y = 1.9875691500e-4f;
    y = fmaf(y, r, 1.3981999507e-3f);
    y = fmaf(y, r, 8.3334519073e-3f);
    y = fmaf(y, r, 4.1665795894e-2f);
    y = fmaf(y, r, 1.6666665459e-1f);
    y = fmaf(y, r, 5.0000001201e-1f);
    y = fmaf(y, z, r);
    y = __fadd_rn(y, 1.0f);
    int n = (int)fx;
    float scale = __int_as_float((n + 127) << 23);
    return __fmul_rn(y, scale);
}

__device__ __forceinline__ float ref_sigmoid(float x) {
    return __fdiv_rn(1.0f, __fadd_rn(1.0f, ref_expf(-x)));
}

// ---------------- kernels ----------------
// k_iou: exact si + logit thresholds; zeroes all counters.
__global__ __launch_bounds__(256) void k_iou(const float* __restrict__ iou) {
    int t = blockIdx.x * 256 + threadIdx.x;
    if (t < NB*HW/4) {
        float4 iv = reinterpret_cast<const float4*>(iou)[t];
        float s0 = ref_sigmoid(iv.x), s1 = ref_sigmoid(iv.y);
        float s2 = ref_sigmoid(iv.z), s3 = ref_sigmoid(iv.w);
        float t0 = (s0 > SI_MIN) ? -logf(fmaf(s0, INV_T2, -1.0f)) : 1e30f;
        float t1 = (s1 > SI_MIN) ? -logf(fmaf(s1, INV_T2, -1.0f)) : 1e30f;
        float t2 = (s2 > SI_MIN) ? -logf(fmaf(s2, INV_T2, -1.0f)) : 1e30f;
        float t3 = (s3 > SI_MIN) ? -logf(fmaf(s3, INV_T2, -1.0f)) : 1e30f;
        reinterpret_cast<float4*>(g_siou)[t] = make_float4(s0, s1, s2, s3);
        reinterpret_cast<float4*>(g_xthr)[t] = make_float4(t0, t1, t2, t3);
    }
    // zero scratch: 2*NB*NBINS + 4*NB = 114720 < 121600 threads
    if (t < NB*NBINS)                 (&g_fhist[0][0])[t] = 0;
    else if (t < 2*NB*NBINS)          (&g_cursor[0][0])[t - NB*NBINS] = 0;
    else {
        int q = t - 2*NB*NBINS;
        if (q < NB)           g_FB[q] = 0;
        else if (q < 2*NB)    g_hotcnt[q - NB] = 0;
        else if (q < 3*NB)    g_coldcnt[q - 2*NB] = 0;
        else if (q < 4*NB)    g_hotovf[q - 3*NB] = 0;
    }
}

// Fused sweep + exact pass. Pass 1 is now FULLY COALESCED: consecutive lanes
// load consecutive float4s (thread t takes float4 #t and #(t+256) of the
// block's 2048-element span; both loads front-batched, xthr read full-res
// from L2, coalesced). float4s never straddle channels (e%4==0, HW%4==0).
// Pass 2 (block-local, unchanged): exact verified score, exact 0.80 cut,
// hist atomic, keys -> shared hot/cold lists, ONE aggregated append each.
__global__ __launch_bounds__(256) void k_main(const float* __restrict__ cls) {
    __shared__ int2 scand[SLICE_CAP];
    __shared__ unsigned long long sh_hot[SLICE_CAP];
    __shared__ unsigned long long sh_cold[SLICE_CAP];
    __shared__ int scnt, nhot, ncold, hbase, cbase;
    if (threadIdx.x == 0) { scnt = 0; nhot = 0; ncold = 0; }
    __syncthreads();

    int n = blockIdx.y;
    int base = blockIdx.x * ELEM_PER_BLK;
    const float* img = cls + (size_t)n * CHW;

    int e0 = base + threadIdx.x * 4;
    int e1 = e0 + 1024;
    int c0 = e0 / HW, hw0 = e0 - c0 * HW;
    int c1 = e1 / HW, hw1 = e1 - c1 * HW;

    // front-batched loads: 2x DRAM (cls) + 2x L2 (xthr)
    float4 xv0 = *reinterpret_cast<const float4*>(img + e0);
    float4 xv1 = *reinterpret_cast<const float4*>(img + e1);
    float4 xt0 = *reinterpret_cast<const float4*>(&g_xthr[n * HW + hw0]);
    float4 xt1 = *reinterpret_cast<const float4*>(&g_xthr[n * HW + hw1]);

    {
        float xs[4] = {xv0.x, xv0.y, xv0.z, xv0.w};
        float ts[4] = {xt0.x, xt0.y, xt0.z, xt0.w};
        #pragma unroll
        for (int j = 0; j < 4; j++) {
            if (xs[j] > ts[j]) {
                int pos = atomicAdd(&scnt, 1);
                if (pos < SLICE_CAP)
                    scand[pos] = make_int2(e0 + j, __float_as_int(xs[j]));
            }
        }
    }
    {
        float xs[4] = {xv1.x, xv1.y, xv1.z, xv1.w};
        float ts[4] = {xt1.x, xt1.y, xt1.z, xt1.w};
        #pragma unroll
        for (int j = 0; j < 4; j++) {
            if (xs[j] > ts[j]) {
                int pos = atomicAdd(&scnt, 1);
                if (pos < SLICE_CAP)
                    scand[pos] = make_int2(e1 + j, __float_as_int(xs[j]));
            }
        }
    }
    __syncthreads();

    int cnt = scnt < SLICE_CAP ? scnt : SLICE_CAP;
    for (int j = threadIdx.x; j < cnt; j += 256) {
        int e = scand[j].x;
        float x = __int_as_float(scand[j].y);
        int cc = e / HW;
        int ehw = e - cc * HW;
        float si = g_siou[n * HW + ehw];
        float sc = ref_sigmoid(x);
        float score = __fsqrt_rn(__fmul_rn(sc, si));
        if (score > KEEP_CUT) {
            unsigned sb = __float_as_uint(score);
            int fbin = (int)((sb - BIN_BASE) >> 9);
            atomicAdd(&g_fhist[n][fbin], 1);
            int idx = ehw * NC + cc;                   // flat [HWA*C] index
            unsigned long long key =
                ((unsigned long long)sb << 24) | (unsigned)(0xFFFFFF - idx);
            if (sb >= HOT_BITS) {
                int s = atomicAdd(&nhot, 1);
                sh_hot[s] = key;
            } else {
                int s = atomicAdd(&ncold, 1);
                sh_cold[s] = key;
            }
        }
    }
    __syncthreads();
    if (threadIdx.x == 0) {
        if (nhot > 0)  hbase = atomicAdd(&g_hotcnt[n], nhot);
        if (ncold > 0) cbase = atomicAdd(&g_coldcnt[n], ncold);
    }
    __syncthreads();
    for (int i = threadIdx.x; i < nhot; i += 256) {
        int pp = hbase + i;
        if (pp < HOTCAP) g_hot[n][pp] = sh_hot[i];
        else {                                          // overflow: spill to cold
            g_hotovf[n] = 1;
            int q = atomicAdd(&g_coldcnt[n], 1);
            if (q < COLDCAP) g_cold[n][q] = sh_hot[i];
        }
    }
    for (int i = threadIdx.x; i < ncold; i += 256) {
        int pp = cbase + i;
        if (pp < COLDCAP) g_cold[n][pp] = sh_cold[i];
    }
}

// Parallel suffix scan: 1024 threads/image, 7 bins/thread in registers.
__global__ __launch_bounds__(1024) void k_scan() {
    int n = blockIdx.x;
    int t = threadIdx.x;
    const int per = NBINS / 1024;   // 7
    int base = t * per;
    int v[per];
    int sum = 0;
    #pragma unroll
    for (int i = 0; i < per; i++) { v[i] = g_fhist[n][base + i]; sum += v[i]; }

    __shared__ int warpsum[32];
    int lane = t & 31, wid = t >> 5;
    int incl = sum;
    #pragma unroll
    for (int off = 1; off < 32; off <<= 1) {
        int x = __shfl_up_sync(0xFFFFFFFFu, incl, off);
        if (lane >= off) incl += x;
    }
    if (lane == 31) warpsum[wid] = incl;
    __syncthreads();
    if (wid == 0) {
        int w = warpsum[lane];
        #pragma unroll
        for (int off = 1; off < 32; off <<= 1) {
            int x = __shfl_up_sync(0xFFFFFFFFu, w, off);
            if (lane >= off) w += x;
        }
        warpsum[lane] = w;
    }
    __syncthreads();
    int total = warpsum[31];
    if (wid > 0) incl += warpsum[wid - 1];
    int run = total - incl;

    #pragma unroll
    for (int i = per - 1; i >= 0; i--) {
        int b = base + i;
        int h = v[i];
        g_cabove[n][b] = run;
        if (run < KTOP && run + h >= KTOP) g_FB[n] = b;   // unique
        run += h;
    }
}

// Counting-sort scatter: hot keys always; cold only if FB below hot cut
// or hot overflow (expected: never).
__global__ __launch_bounds__(256) void k_scatter() {
    int n = blockIdx.y;
    int fb = g_FB[n];
    int stride = gridDim.x * 256;
    int t0 = blockIdx.x * 256 + threadIdx.x;

    int hot = g_hotcnt[n];
    if (hot > HOTCAP) hot = HOTCAP;
    for (int j = t0; j < hot; j += stride) {
        unsigned long long key = g_hot[n][j];
        unsigned sb = (unsigned)(key >> 24);
        int fbin = (int)((sb - BIN_BASE) >> 9);
        if (fbin < fb) continue;
        int pos = g_cabove[n][fbin] + atomicAdd(&g_cursor[n][fbin], 1);
        if (pos < KTOP + PAD) g_sorted[n][pos] = key;
    }
    if (fb < HOT_FBIN || g_hotovf[n]) {
        int cold = g_coldcnt[n];
        if (cold > COLDCAP) cold = COLDCAP;
        for (int j = t0; j < cold; j += stride) {
            unsigned long long key = g_cold[n][j];
            unsigned sb = (unsigned)(key >> 24);
            int fbin = (int)((sb - BIN_BASE) >> 9);
            if (fbin < fb) continue;
            int pos = g_cabove[n][fbin] + atomicAdd(&g_cursor[n][fbin], 1);
            if (pos < KTOP + PAD) g_sorted[n][pos] = key;
        }
    }
}

// Within-bin fixup (bins ~2-7 items near threshold; 64-slot cap).
__global__ __launch_bounds__(256) void k_fix() {
    int n = blockIdx.y;
    int b = blockIdx.x * 256 + threadIdx.x;
    if (b >= NBINS || b < g_FB[n]) return;
    int len = g_cursor[n][b];
    if (len < 2) return;
    int start = g_cabove[n][b];
    int end = start + len;
    if (end > KTOP + PAD) end = KTOP + PAD;
    len = end - start;
    if (len < 2) return;
    if (len > 64) len = 64;
    unsigned long long a[64];
    for (int i = 0; i < len; i++) a[i] = g_sorted[n][start + i];
    for (int i = 1; i < len; i++) {
        unsigned long long vv = a[i];
        int j = i - 1;
        while (j >= 0 && a[j] < vv) { a[j+1] = a[j]; j--; }
        a[j+1] = vv;
    }
    for (int i = 0; i < len; i++) g_sorted[n][start + i] = a[i];
}

// Decode + emit boxes[N,K,5] then labels[N,K].
__global__ __launch_bounds__(256) void k_out(const float* __restrict__ reg,
                                             const float* __restrict__ anchors,
                                             float* __restrict__ out,
                                             int has_labels) {
    int t = blockIdx.x * 256 + threadIdx.x;
    if (t >= NB * KTOP) return;
    int n = t / KTOP;
    int k = t - n * KTOP;
    unsigned long long key = g_sorted[n][k];
    float score = __uint_as_float((unsigned)(key >> 24));
    int idx = 0xFFFFFF - (int)(key & 0xFFFFFF);
    int loc = idx / NC;
    int c = idx - loc * NC;

    float4 anc = reinterpret_cast<const float4*>(anchors)[loc];
    const float* rb = reg + (size_t)n * 4 * HW + loc;
    float r0 = __ldg(rb), r1 = __ldg(rb + HW), r2 = __ldg(rb + 2*HW), r3 = __ldg(rb + 3*HW);

    float wdt = anc.z - anc.x + 1.0f;
    float hgt = anc.w - anc.y + 1.0f;
    float cx = anc.x + 0.5f * wdt;
    float cy = anc.y + 0.5f * hgt;
    float dx = __fdiv_rn(r0, 10.0f);
    float dy = __fdiv_rn(r1, 10.0f);
    float dw = fminf(__fdiv_rn(r2, 5.0f), BBOX_CLIP);
    float dh = fminf(__fdiv_rn(r3, 5.0f), BBOX_CLIP);
    float pcx = dx * wdt + cx;
    float pcy = dy * hgt + cy;
    float pw = expf(dw) * wdt;
    float ph = expf(dh) * hgt;
    float x1 = pcx - 0.5f * pw;
    float y1 = pcy - 0.5f * ph;
    float x2 = pcx + 0.5f * pw - 1.0f;
    float y2 = pcy + 0.5f * ph - 1.0f;
    x1 = fminf(fmaxf(x1, 0.0f), IMG_W_M1);
    y1 = fminf(fmaxf(y1, 0.0f), IMG_H_M1);
    x2 = fminf(fmaxf(x2, 0.0f), IMG_W_M1);
    y2 = fminf(fmaxf(y2, 0.0f), IMG_H_M1);

    float* o = out + (size_t)t * 5;
    o[0] = x1; o[1] = y1; o[2] = x2; o[3] = y2; o[4] = score;
    if (has_labels) out[NB * KTOP * 5 + t] = (float)(c + 1);
}

// ---------------- launch ----------------
extern "C" void kernel_launch(void* const* d_in, const int* in_sizes, int n_in,
                              void* d_out, int out_size) {
    const float* cls = (const float*)d_in[0];
    const float* reg = (const float*)d_in[1];
    const float* iou = (const float*)d_in[2];
    const float* anc = (const float*)d_in[3];
    float* out = (float*)d_out;
    int has_labels = (out_size >= NB * KTOP * 6) ? 1 : 0;

    k_iou    <<<(NB*HW/4 + 255) / 256, 256>>>(iou);   // + zero counters
    { dim3 g(BLKS_PER_IMG, NB); k_main<<<g, 256>>>(cls); }
    k_scan   <<<NB, 1024>>>();
    { dim3 g(16, NB); k_scatter<<<g, 256>>>(); }
    { dim3 g(NBINS/256, NB); k_fix<<<g, 256>>>(); }
    k_out    <<<(NB * KTOP + 255) / 256, 256>>>(reg, anc, out, has_labels);
}

// round 15
// speedup vs baseline: 1.2892x; 1.2892x over previous
#include <cuda_runtime.h>
#include <cstdint>
#include <math.h>

// ---------------- problem constants ----------------
#define NB   8
#define NC   80
#define NH   200
#define NW   304
#define HW   (NH*NW)            // 60800
#define CHW  (NC*HW)            // 4,864,000
#define KTOP 10000
#define PAD  512

// Histogram rebased at the keep-cut: kept scores have sb >= 0x3F4CCCCE.
#define BIN_BASE 0x3F4CCCCEu
#define NBINS 7168              // 28 * 256

// Hot/cold key split at fine-bin 1966 boundary (score ~0.85996).
#define HOT_BITS 0x3F5C28CEu
#define HOT_FBIN 1966
#define HOTCAP  65536
#define COLDCAP 131072

#define HW_TILE 1024            // hw positions per block (256 thr x 4)
#define HW_BLKS 60              // ceil(60800/1024)
#define CGRPS   20              // 80 channels / 4 per thread
#define SLICE_CAP 512

#define FIN_BLKS 40             // finish kernel blocks per image

#define IMG_W_M1 2431.0f
#define IMG_H_M1 1599.0f
#define BBOX_CLIP 4.135166556742356f   // log(1000/16)

// Exact keep-cut (verified rounds 5-14): score > 0.80.
#define KEEP_CUT 0.80f
// Pass-1 loose cut T=0.79: x > xthr(si) = -log(si/T^2 - 1); logit margin
// to the exact cut >= 0.026 -> pass-1 can only over-keep.
#define INV_T2 1.602307322f        // 1/0.6241
#define SI_MIN 0.6242f

// ---------------- device scratch ----------------
__device__ float               g_siou[NB*HW];
__device__ float               g_xthr[NB*HW];
__device__ int                 g_fhist[NB][NBINS];
__device__ int                 g_cabove[NB][NBINS];
__device__ int                 g_cursor[NB][NBINS];
__device__ int                 g_FB[NB];
__device__ int                 g_hotcnt[NB];
__device__ int                 g_coldcnt[NB];
__device__ int                 g_hotovf[NB];
__device__ int                 g_ph_scan[NB];
__device__ int                 g_ph_scat[NB];
__device__ int                 g_ph_fix[NB];
__device__ unsigned long long  g_hot[NB][HOTCAP];
__device__ unsigned long long  g_cold[NB][COLDCAP];
__device__ unsigned long long  g_sorted[NB][KTOP+PAD];

// ---------------- reference-exact sigmoid: FUSED Cephes exp ----------------
// (verified bit-exact vs reference in rounds 5-14: rel_err 7.2e-9)
__device__ __forceinline__ float ref_expf(float a) {
    float x = fminf(a, 88.3762626647950f);
    x = fmaxf(x, -88.3762626647949f);
    float fx = floorf(fmaf(x, 1.44269504088896341f, 0.5f));
    float r = fmaf(-0.693359375f, fx, x);
    r = fmaf(2.12194440e-4f, fx, r);
    float z = __fmul_rn(r, r);
    float y = 1.9875691500e-4f;
    y = fmaf(y, r, 1.3981999507e-3f);
    y = fmaf(y, r, 8.3334519073e-3f);
    y = fmaf(y, r, 4.1665795894e-2f);
    y = fmaf(y, r, 1.6666665459e-1f);
    y = fmaf(y, r, 5.0000001201e-1f);
    y = fmaf(y, z, r);
    y = __fadd_rn(y, 1.0f);
    int n = (int)fx;
    float scale = __int_as_float((n + 127) << 23);
    return __fmul_rn(y, scale);
}

__device__ __forceinline__ float ref_sigmoid(float x) {
    return __fdiv_rn(1.0f, __fadd_rn(1.0f, ref_expf(-x)));
}

// ---------------- kernels ----------------
// k_iou: exact si + logit thresholds; zeroes all counters.
__global__ __launch_bounds__(256) void k_iou(const float* __restrict__ iou) {
    int t = blockIdx.x * 256 + threadIdx.x;
    if (t < NB*HW/4) {
        float4 iv = reinterpret_cast<const float4*>(iou)[t];
        float s0 = ref_sigmoid(iv.x), s1 = ref_sigmoid(iv.y);
        float s2 = ref_sigmoid(iv.z), s3 = ref_sigmoid(iv.w);
        float t0 = (s0 > SI_MIN) ? -logf(fmaf(s0, INV_T2, -1.0f)) : 1e30f;
        float t1 = (s1 > SI_MIN) ? -logf(fmaf(s1, INV_T2, -1.0f)) : 1e30f;
        float t2 = (s2 > SI_MIN) ? -logf(fmaf(s2, INV_T2, -1.0f)) : 1e30f;
        float t3 = (s3 > SI_MIN) ? -logf(fmaf(s3, INV_T2, -1.0f)) : 1e30f;
        reinterpret_cast<float4*>(g_siou)[t] = make_float4(s0, s1, s2, s3);
        reinterpret_cast<float4*>(g_xthr)[t] = make_float4(t0, t1, t2, t3);
    }
    // zero scratch: 2*NB*NBINS + 7*NB = 114744 < 121600 threads
    if (t < NB*NBINS)                 (&g_fhist[0][0])[t] = 0;
    else if (t < 2*NB*NBINS)          (&g_cursor[0][0])[t - NB*NBINS] = 0;
    else {
        int q = t - 2*NB*NBINS;
        if (q < NB)           g_FB[q] = 0;
        else if (q < 2*NB)    g_hotcnt[q - NB] = 0;
        else if (q < 3*NB)    g_coldcnt[q - 2*NB] = 0;
        else if (q < 4*NB)    g_hotovf[q - 3*NB] = 0;
        else if (q < 5*NB)    g_ph_scan[q - 4*NB] = 0;
        else if (q < 6*NB)    g_ph_scat[q - 5*NB] = 0;
        else if (q < 7*NB)    g_ph_fix[q - 6*NB] = 0;
    }
}

// Fused sweep + exact pass. Pass 1: thread owns the SAME 4 hw positions
// across 4 consecutive channels -> ONE xthr float4 serves 4 coalesced cls
// float4 loads (L2 side-traffic cut 4x). Pass 2 (block-local, verified):
// exact score, exact 0.80 cut, hist atomic, keys -> shared hot/cold lists,
// one aggregated contiguous append per list.
__global__ __launch_bounds__(256) void k_main(const float* __restrict__ cls) {
    __shared__ int2 scand[SLICE_CAP];
    __shared__ unsigned long long sh_hot[SLICE_CAP];
    __shared__ unsigned long long sh_cold[SLICE_CAP];
    __shared__ int scnt, nhot, ncold, hbase, cbase;
    if (threadIdx.x == 0) { scnt = 0; nhot = 0; ncold = 0; }
    __syncthreads();

    int n  = blockIdx.z;
    int c0 = blockIdx.y * 4;
    int hw0 = blockIdx.x * HW_TILE + threadIdx.x * 4;

    if (hw0 < HW) {                         // HW%4==0 -> full float4 in-bounds
        const float* img = cls + (size_t)n * CHW;
        float4 xt = *reinterpret_cast<const float4*>(&g_xthr[n * HW + hw0]);
        float4 va = *reinterpret_cast<const float4*>(img + (size_t)(c0+0) * HW + hw0);
        float4 vb = *reinterpret_cast<const float4*>(img + (size_t)(c0+1) * HW + hw0);
        float4 vc = *reinterpret_cast<const float4*>(img + (size_t)(c0+2) * HW + hw0);
        float4 vd = *reinterpret_cast<const float4*>(img + (size_t)(c0+3) * HW + hw0);
        float ts[4] = {xt.x, xt.y, xt.z, xt.w};
        float4 vv[4] = {va, vb, vc, vd};
        #pragma unroll
        for (int k = 0; k < 4; k++) {
            float xs[4] = {vv[k].x, vv[k].y, vv[k].z, vv[k].w};
            int ebase = (c0 + k) * HW + hw0;
            #pragma unroll
            for (int j = 0; j < 4; j++) {
                if (xs[j] > ts[j]) {
                    int pos = atomicAdd(&scnt, 1);
                    if (pos < SLICE_CAP)
                        scand[pos] = make_int2(ebase + j, __float_as_int(xs[j]));
                }
            }
        }
    }
    __syncthreads();

    int cnt = scnt < SLICE_CAP ? scnt : SLICE_CAP;
    for (int j = threadIdx.x; j < cnt; j += 256) {
        int e = scand[j].x;
        float x = __int_as_float(scand[j].y);
        int cc = e / HW;
        int ehw = e - cc * HW;
        float si = g_siou[n * HW + ehw];
        float sc = ref_sigmoid(x);
        float score = __fsqrt_rn(__fmul_rn(sc, si));
        if (score > KEEP_CUT) {
            unsigned sb = __float_as_uint(score);
            int fbin = (int)((sb - BIN_BASE) >> 9);
            atomicAdd(&g_fhist[n][fbin], 1);
            int idx = ehw * NC + cc;                   // flat [HWA*C] index
            unsigned long long key =
                ((unsigned long long)sb << 24) | (unsigned)(0xFFFFFF - idx);
            if (sb >= HOT_BITS) {
                int s = atomicAdd(&nhot, 1);
                sh_hot[s] = key;
            } else {
                int s = atomicAdd(&ncold, 1);
                sh_cold[s] = key;
            }
        }
    }
    __syncthreads();
    if (threadIdx.x == 0) {
        if (nhot > 0)  hbase = atomicAdd(&g_hotcnt[n], nhot);
        if (ncold > 0) cbase = atomicAdd(&g_coldcnt[n], ncold);
    }
    __syncthreads();
    for (int i = threadIdx.x; i < nhot; i += 256) {
        int pp = hbase + i;
        if (pp < HOTCAP) g_hot[n][pp] = sh_hot[i];
        else {                                          // overflow: spill to cold
            g_hotovf[n] = 1;
            int q = atomicAdd(&g_coldcnt[n], 1);
            if (q < COLDCAP) g_cold[n][q] = sh_hot[i];
        }
    }
    for (int i = threadIdx.x; i < ncold; i += 256) {
        int pp = cbase + i;
        if (pp < COLDCAP) g_cold[n][pp] = sh_cold[i];
    }
}

// Merged finish (R11 spin-barrier skeleton, exonerated by the R11/R12 A/B,
// + the fast hot/cold store): scan -> scatter -> fix -> out. Grid (40, NB)
// = 320 blocks, __launch_bounds__(256,4) -> >=592 resident -> co-resident,
// spins cannot deadlock. Cross-block reads after barriers use __ldcg.
__global__ __launch_bounds__(256, 4) void k_finish(const float* __restrict__ reg,
                                                   const float* __restrict__ anchors,
                                                   float* __restrict__ out,
                                                   int has_labels) {
    int n  = blockIdx.y;
    int bx = blockIdx.x;
    int tid = threadIdx.x;

    // ---- Phase A: suffix scan (block 0 of each image) ----
    if (bx == 0) {
        const int per = NBINS / 256;   // 28
        int base = tid * per;
        int v[28];
        int sum = 0;
        #pragma unroll
        for (int i = 0; i < per; i++) { v[i] = g_fhist[n][base + i]; sum += v[i]; }

        __shared__ int warpsum[8];
        int lane = tid & 31, wd = tid >> 5;
        int incl = sum;
        #pragma unroll
        for (int off = 1; off < 32; off <<= 1) {
            int x = __shfl_up_sync(0xFFFFFFFFu, incl, off);
            if (lane >= off) incl += x;
        }
        if (lane == 31) warpsum[wd] = incl;
        __syncthreads();
        if (tid < 8) {
            int w = warpsum[tid];
            #pragma unroll
            for (int off = 1; off < 8; off <<= 1) {
                int x = __shfl_up_sync(0x000000FFu, w, off);
                if (tid >= off) w += x;
            }
            warpsum[tid] = w;
        }
        __syncthreads();
        int total = warpsum[7];
        if (wd > 0) incl += warpsum[wd - 1];
        int run = total - incl;
        #pragma unroll
        for (int i = per - 1; i >= 0; i--) {
            int b = base + i;
            int h = v[i];
            g_cabove[n][b] = run;
            if (run < KTOP && run + h >= KTOP) g_FB[n] = b;   // unique
            run += h;
        }
        __syncthreads();
        __threadfence();
        if (tid == 0) atomicExch(&g_ph_scan[n], 1);
    }
    if (tid == 0) { while (atomicAdd(&g_ph_scan[n], 0) == 0) __nanosleep(64); }
    __syncthreads();

    // ---- Phase B: scatter (hot always; cold only if needed) ----
    int fb = __ldcg(&g_FB[n]);
    {
        int stride = FIN_BLKS * 256;
        int t0 = bx * 256 + tid;
        int hot = __ldcg(&g_hotcnt[n]);
        if (hot > HOTCAP) hot = HOTCAP;
        for (int j = t0; j < hot; j += stride) {
            unsigned long long key = g_hot[n][j];
            unsigned sb = (unsigned)(key >> 24);
            int fbin = (int)((sb - BIN_BASE) >> 9);
            if (fbin < fb) continue;
            int pos = __ldcg(&g_cabove[n][fbin]) + atomicAdd(&g_cursor[n][fbin], 1);
            if (pos < KTOP + PAD) g_sorted[n][pos] = key;
        }
        if (fb < HOT_FBIN || __ldcg(&g_hotovf[n])) {
            int cold = __ldcg(&g_coldcnt[n]);
            if (cold > COLDCAP) cold = COLDCAP;
            for (int j = t0; j < cold; j += stride) {
                unsigned long long key = g_cold[n][j];
                unsigned sb = (unsigned)(key >> 24);
                int fbin = (int)((sb - BIN_BASE) >> 9);
                if (fbin < fb) continue;
                int pos = __ldcg(&g_cabove[n][fbin]) + atomicAdd(&g_cursor[n][fbin], 1);
                if (pos < KTOP + PAD) g_sorted[n][pos] = key;
            }
        }
    }
    __threadfence();
    __syncthreads();
    if (tid == 0) {
        atomicAdd(&g_ph_scat[n], 1);
        while (atomicAdd(&g_ph_scat[n], 0) < FIN_BLKS) __nanosleep(64);
    }
    __syncthreads();

    // ---- Phase C: within-bin fixup ----
    {
        int b = bx * 256 + tid;                 // 10240 threads >= NBINS
        if (b < NBINS && b >= fb) {
            int len = atomicAdd(&g_cursor[n][b], 0);
            if (len >= 2) {
                int start = __ldcg(&g_cabove[n][b]);
                int end = start + len;
                if (end > KTOP + PAD) end = KTOP + PAD;
                len = end - start;
                if (len > 64) len = 64;
                if (len >= 2) {
                    unsigned long long a[64];
                    for (int i = 0; i < len; i++) a[i] = __ldcg(&g_sorted[n][start + i]);
                    for (int i = 1; i < len; i++) {
                        unsigned long long vv = a[i];
                        int j = i - 1;
                        while (j >= 0 && a[j] < vv) { a[j+1] = a[j]; j--; }
                        a[j+1] = vv;
                    }
                    for (int i = 0; i < len; i++) g_sorted[n][start + i] = a[i];
                }
            }
        }
    }
    __threadfence();
    __syncthreads();
    if (tid == 0) {
        atomicAdd(&g_ph_fix[n], 1);
        while (atomicAdd(&g_ph_fix[n], 0) < FIN_BLKS) __nanosleep(64);
    }
    __syncthreads();

    // ---- Phase D: decode + emit ----
    int k = bx * 256 + tid;
    if (k < KTOP) {
        unsigned long long key = __ldcg(&g_sorted[n][k]);
        float score = __uint_as_float((unsigned)(key >> 24));
        int idx = 0xFFFFFF - (int)(key & 0xFFFFFF);
        int loc = idx / NC;
        int c = idx - loc * NC;

        float4 anc = reinterpret_cast<const float4*>(anchors)[loc];
        const float* rb = reg + (size_t)n * 4 * HW + loc;
        float r0 = __ldg(rb), r1 = __ldg(rb + HW), r2 = __ldg(rb + 2*HW), r3 = __ldg(rb + 3*HW);

        float wdt = anc.z - anc.x + 1.0f;
        float hgt = anc.w - anc.y + 1.0f;
        float cx = anc.x + 0.5f * wdt;
        float cy = anc.y + 0.5f * hgt;
        float dx = __fdiv_rn(r0, 10.0f);
        float dy = __fdiv_rn(r1, 10.0f);
        float dw = fminf(__fdiv_rn(r2, 5.0f), BBOX_CLIP);
        float dh = fminf(__fdiv_rn(r3, 5.0f), BBOX_CLIP);
        float pcx = dx * wdt + cx;
        float pcy = dy * hgt + cy;
        float pw = expf(dw) * wdt;
        float ph = expf(dh) * hgt;
        float x1 = pcx - 0.5f * pw;
        float y1 = pcy - 0.5f * ph;
        float x2 = pcx + 0.5f * pw - 1.0f;
        float y2 = pcy + 0.5f * ph - 1.0f;
        x1 = fminf(fmaxf(x1, 0.0f), IMG_W_M1);
        y1 = fminf(fmaxf(y1, 0.0f), IMG_H_M1);
        x2 = fminf(fmaxf(x2, 0.0f), IMG_W_M1);
        y2 = fminf(fmaxf(y2, 0.0f), IMG_H_M1);

        int t = n * KTOP + k;
        float* o = out + (size_t)t * 5;
        o[0] = x1; o[1] = y1; o[2] = x2; o[3] = y2; o[4] = score;
        if (has_labels) out[NB * KTOP * 5 + t] = (float)(c + 1);
    }
}

// ---------------- launch ----------------
extern "C" void kernel_launch(void* const* d_in, const int* in_sizes, int n_in,
                              void* d_out, int out_size) {
    const float* cls = (const float*)d_in[0];
    const float* reg = (const float*)d_in[1];
    const float* iou = (const float*)d_in[2];
    const float* anc = (const float*)d_in[3];
    float* out = (float*)d_out;
    int has_labels = (out_size >= NB * KTOP * 6) ? 1 : 0;

    k_iou    <<<(NB*HW/4 + 255) / 256, 256>>>(iou);   // + zero counters
    { dim3 g(HW_BLKS, CGRPS, NB); k_main<<<g, 256>>>(cls); }
    { dim3 g(FIN_BLKS, NB);       k_finish<<<g, 256>>>(reg, anc, out, has_labels); }
}